// round 1
// baseline (speedup 1.0000x reference)
#include <cuda_runtime.h>
#include <cuda_bf16.h>
#include <stdint.h>

// Problem constants (fixed shapes from setup_inputs)
#define B_SZ 32
#define C_SZ 512
#define T_PH 1024
#define MAX_FRAMES 8192   // durations < 8 -> total < 8*1024

// Scratch: frame -> phone index map, and per-batch totals.
__device__ int g_f2p[B_SZ * MAX_FRAMES];
__device__ int g_total[B_SZ];

// -----------------------------------------------------------------------------
// Kernel 1: per-batch inclusive scan of durations (T_PH=1024 threads/block),
// scatter phone index into frame2phone, zero-fill the invalid tail, and write
// the mel_mask (as float 1.0/0.0) if requested.
// -----------------------------------------------------------------------------
__global__ void __launch_bounds__(T_PH)
lr_scan_scatter_kernel(const int* __restrict__ durations,
                       float* __restrict__ mask_out,   // nullptr if no mask
                       int M)
{
    const int b   = blockIdx.x;
    const int tid = threadIdx.x;

    __shared__ int s[T_PH];

    int d = durations[b * T_PH + tid];
    s[tid] = d;
    __syncthreads();

    // Hillis-Steele inclusive scan
    #pragma unroll
    for (int off = 1; off < T_PH; off <<= 1) {
        int v   = s[tid];
        int add = (tid >= off) ? s[tid - off] : 0;
        __syncthreads();
        s[tid] = v + add;
        __syncthreads();
    }

    const int incl  = s[tid];
    const int excl  = incl - d;
    const int total = s[T_PH - 1];

    if (tid == 0) g_total[b] = total;

    // Scatter: phone tid covers frames [excl, incl)  (d <= 7 iterations)
    int* f2p = g_f2p + b * MAX_FRAMES;
    for (int t = excl; t < incl; ++t) f2p[t] = tid;

    // Zero-fill invalid tail so the gather kernel never reads garbage indices
    for (int t = total + tid; t < M; t += T_PH) f2p[t] = 0;

    // mel_mask[b][t] = (t >= total)
    if (mask_out) {
        for (int t = tid; t < M; t += T_PH)
            mask_out[b * M + t] = (t >= total) ? 1.0f : 0.0f;
    }
}

// -----------------------------------------------------------------------------
// Kernel 2: the big gather.
//   out[b][c][t] = (t < total[b]) ? x[b][c][f2p[b][t]] : 0
// Coalesced float4 stores along t. x-row (4KB) is L1-resident; indices are
// monotone non-decreasing across the warp -> good locality.
// grid = (ceil(M/1024), C, B), block = 256, 4 frames/thread.
// -----------------------------------------------------------------------------
__global__ void __launch_bounds__(256)
lr_gather_kernel(const float* __restrict__ x,
                 float* __restrict__ out,
                 int M)
{
    const int b = blockIdx.z;
    const int c = blockIdx.y;
    const int t0 = (blockIdx.x * 256 + threadIdx.x) * 4;
    if (t0 >= M) return;

    const int total = g_total[b];
    const int* __restrict__ f2p = g_f2p + b * MAX_FRAMES;

    const float* __restrict__ xr = x + ((size_t)(b * C_SZ + c)) * T_PH;
    float* __restrict__ orow = out + ((size_t)(b * C_SZ + c)) * M;

    if (t0 + 3 < M) {
        int4 p = *reinterpret_cast<const int4*>(f2p + t0);
        float4 v;
        v.x = (t0 + 0 < total) ? __ldg(xr + p.x) : 0.0f;
        v.y = (t0 + 1 < total) ? __ldg(xr + p.y) : 0.0f;
        v.z = (t0 + 2 < total) ? __ldg(xr + p.z) : 0.0f;
        v.w = (t0 + 3 < total) ? __ldg(xr + p.w) : 0.0f;
        *reinterpret_cast<float4*>(orow + t0) = v;
    } else {
        for (int t = t0; t < M; ++t) {
            int p = f2p[t];
            orow[t] = (t < total) ? __ldg(xr + p) : 0.0f;
        }
    }
}

// -----------------------------------------------------------------------------
// Launch
// -----------------------------------------------------------------------------
extern "C" void kernel_launch(void* const* d_in, const int* in_sizes, int n_in,
                              void* d_out, int out_size)
{
    const float* x         = (const float*)d_in[0];
    const int*   durations = (const int*)d_in[1];
    float* out = (float*)d_out;

    // Resolve max_frames (M) and output layout from out_size.
    // Preferred: tuple layout  out[B,C,M] ++ mask[B,M]  => out_size = B*M*(C+1)
    // Fallback:  out-only      out[B,C,M]               => out_size = B*M*C
    long long os = (long long)out_size;
    int M;
    float* mask_ptr = nullptr;
    if (os % ((long long)B_SZ * (C_SZ + 1)) == 0) {
        M = (int)(os / ((long long)B_SZ * (C_SZ + 1)));
        mask_ptr = out + (size_t)B_SZ * C_SZ * M;
    } else {
        M = (int)(os / ((long long)B_SZ * C_SZ));
    }

    // Pass 1: scan + scatter + mask
    lr_scan_scatter_kernel<<<B_SZ, T_PH>>>(durations, mask_ptr, M);

    // Pass 2: gather
    dim3 grid((M + 1023) / 1024, C_SZ, B_SZ);
    lr_gather_kernel<<<grid, 256>>>(x, out, M);
}

// round 2
// speedup vs baseline: 1.2248x; 1.2248x over previous
#include <cuda_runtime.h>
#include <cuda_bf16.h>
#include <stdint.h>

// Problem constants (fixed shapes from setup_inputs)
#define B_SZ 32
#define C_SZ 512
#define T_PH 1024
#define MAX_FRAMES 8192   // durations < 8 -> total < 8*1024

#define TILE_T 1024       // frames per gather tile
#define CPB    16         // channels per block (f2p smem reuse factor)

// Scratch: frame -> phone index map, and per-batch totals.
__device__ int g_f2p[B_SZ * MAX_FRAMES];
__device__ int g_total[B_SZ];

// -----------------------------------------------------------------------------
// Kernel 1: per-batch inclusive scan of durations (warp-shuffle scan),
// scatter phone index into frame2phone, zero-fill invalid tail, write mask.
// -----------------------------------------------------------------------------
__global__ void __launch_bounds__(T_PH)
lr_scan_scatter_kernel(const int* __restrict__ durations,
                       float* __restrict__ mask_out,   // nullptr if no mask
                       int M)
{
    const int b    = blockIdx.x;
    const int tid  = threadIdx.x;
    const int lane = tid & 31;
    const int wid  = tid >> 5;

    __shared__ int wsum[32];

    int d = durations[b * T_PH + tid];

    // intra-warp inclusive scan
    int v = d;
    #pragma unroll
    for (int off = 1; off < 32; off <<= 1) {
        int n = __shfl_up_sync(0xFFFFFFFFu, v, off);
        if (lane >= off) v += n;
    }
    if (lane == 31) wsum[wid] = v;
    __syncthreads();

    // scan of the 32 warp sums in warp 0
    if (wid == 0) {
        int w = wsum[lane];
        #pragma unroll
        for (int off = 1; off < 32; off <<= 1) {
            int n = __shfl_up_sync(0xFFFFFFFFu, w, off);
            if (lane >= off) w += n;
        }
        wsum[lane] = w;
    }
    __syncthreads();

    const int incl  = v + (wid ? wsum[wid - 1] : 0);
    const int excl  = incl - d;
    const int total = wsum[31];

    if (tid == 0) g_total[b] = total;

    // Scatter: phone tid covers frames [excl, incl)  (d <= 7 iterations)
    int* f2p = g_f2p + b * MAX_FRAMES;
    for (int t = excl; t < incl; ++t) f2p[t] = tid;

    // Zero-fill invalid tail so the gather kernel never reads garbage indices
    for (int t = total + tid; t < M; t += T_PH) f2p[t] = 0;

    // mel_mask[b][t] = (t >= total)
    if (mask_out) {
        for (int t = tid; t < M; t += T_PH)
            mask_out[b * M + t] = (t >= total) ? 1.0f : 0.0f;
    }
}

// -----------------------------------------------------------------------------
// Kernel 2: the big gather, retiled to amortize index reads.
// One block = one (batch, 1024-frame tile) x 16 channels.
// f2p tile loaded into smem ONCE, reused across 16 channels.
//   out[b][c][t] = (t < total[b]) ? x[b][c][f2p[b][t]] : 0
// grid = (ceil(M/TILE_T), C/CPB, B), block = 256, 4 frames/thread/channel.
// -----------------------------------------------------------------------------
__global__ void __launch_bounds__(256)
lr_gather_kernel(const float* __restrict__ x,
                 float* __restrict__ out,
                 int M)
{
    const int b  = blockIdx.z;
    const int t0 = blockIdx.x * TILE_T;          // tile start frame
    const int c0 = blockIdx.y * CPB;             // first channel of this block
    const int tid = threadIdx.x;

    __shared__ int s_f2p[TILE_T];

    const int total = g_total[b];
    const int* __restrict__ f2p = g_f2p + b * MAX_FRAMES;

    // Cooperative load of the f2p tile (vectorized; MAX_FRAMES covers overrun)
    #pragma unroll
    for (int i = tid; i < TILE_T / 4; i += 256) {
        *reinterpret_cast<int4*>(s_f2p + i * 4) =
            *reinterpret_cast<const int4*>(f2p + t0 + i * 4);
    }
    __syncthreads();

    const int tl = t0 + tid * 4;                 // this thread's frame base
    const bool full = (tl + 3 < M);

    int4 p = *reinterpret_cast<const int4*>(s_f2p + tid * 4);

    // validity of the 4 frames (same for every channel)
    const bool v0 = (tl + 0 < total);
    const bool v1 = (tl + 1 < total);
    const bool v2 = (tl + 2 < total);
    const bool v3 = (tl + 3 < total);

    const size_t xbase = (size_t)(b * C_SZ + c0) * T_PH;
    const size_t obase = (size_t)(b * C_SZ + c0) * M;

    if (full) {
        #pragma unroll 4
        for (int c = 0; c < CPB; ++c) {
            const float* __restrict__ xr = x + xbase + (size_t)c * T_PH;
            float4 v;
            v.x = v0 ? __ldg(xr + p.x) : 0.0f;
            v.y = v1 ? __ldg(xr + p.y) : 0.0f;
            v.z = v2 ? __ldg(xr + p.z) : 0.0f;
            v.w = v3 ? __ldg(xr + p.w) : 0.0f;
            *reinterpret_cast<float4*>(out + obase + (size_t)c * M + tl) = v;
        }
    } else if (tl < M) {
        for (int c = 0; c < CPB; ++c) {
            const float* __restrict__ xr = x + xbase + (size_t)c * T_PH;
            float* __restrict__ orow = out + obase + (size_t)c * M;
            for (int t = tl; t < M; ++t) {
                int pp = s_f2p[t - t0];
                orow[t] = (t < total) ? __ldg(xr + pp) : 0.0f;
            }
        }
    }
}

// Scalar-safe fallback gather (used only if M % 4 != 0)
__global__ void __launch_bounds__(256)
lr_gather_scalar_kernel(const float* __restrict__ x,
                        float* __restrict__ out,
                        int M)
{
    const int b = blockIdx.z;
    const int c = blockIdx.y;
    const int t = blockIdx.x * 256 + threadIdx.x;
    if (t >= M) return;
    const int total = g_total[b];
    const int p = g_f2p[b * MAX_FRAMES + t];
    const float* xr = x + (size_t)(b * C_SZ + c) * T_PH;
    out[(size_t)(b * C_SZ + c) * M + t] = (t < total) ? __ldg(xr + p) : 0.0f;
}

// -----------------------------------------------------------------------------
// Launch
// -----------------------------------------------------------------------------
extern "C" void kernel_launch(void* const* d_in, const int* in_sizes, int n_in,
                              void* d_out, int out_size)
{
    const float* x         = (const float*)d_in[0];
    const int*   durations = (const int*)d_in[1];
    float* out = (float*)d_out;

    // Resolve max_frames (M) and output layout from out_size.
    // Preferred: tuple layout  out[B,C,M] ++ mask[B,M]  => out_size = B*M*(C+1)
    // Fallback:  out-only      out[B,C,M]               => out_size = B*M*C
    long long os = (long long)out_size;
    int M;
    float* mask_ptr = nullptr;
    if (os % ((long long)B_SZ * (C_SZ + 1)) == 0) {
        M = (int)(os / ((long long)B_SZ * (C_SZ + 1)));
        mask_ptr = out + (size_t)B_SZ * C_SZ * M;
    } else {
        M = (int)(os / ((long long)B_SZ * C_SZ));
    }

    // Pass 1: scan + scatter + mask
    lr_scan_scatter_kernel<<<B_SZ, T_PH>>>(durations, mask_ptr, M);

    // Pass 2: gather
    if ((M & 3) == 0) {
        dim3 grid((M + TILE_T - 1) / TILE_T, C_SZ / CPB, B_SZ);
        lr_gather_kernel<<<grid, 256>>>(x, out, M);
    } else {
        dim3 grid((M + 255) / 256, C_SZ, B_SZ);
        lr_gather_scalar_kernel<<<grid, 256>>>(x, out, M);
    }
}

// round 3
// speedup vs baseline: 1.3088x; 1.0686x over previous
#include <cuda_runtime.h>
#include <cuda_bf16.h>
#include <stdint.h>

// Problem constants (fixed shapes from setup_inputs)
#define B_SZ 32
#define C_SZ 512
#define T_PH 1024
#define TILE_T 1024       // frames per block tile
#define CPB    16         // channels per block
#define NT     256        // threads per block
#define NW     (NT / 32)  // warps per block

// -----------------------------------------------------------------------------
// Single fused kernel.
// Each block: (batch b, 1024-frame tile, 16-channel group).
//  1. Block-local inclusive scan of durations[b] (1024 ints) into smem.
//  2. Binary search each of this thread's 4 frames -> phone indices.
//  3. Gather x with high MLP (16 loads in flight), float4 stores.
//  4. blockIdx.y==0 blocks also write the mel_mask tile.
// No scratch globals, no inter-kernel dependency, one launch.
// -----------------------------------------------------------------------------
__global__ void __launch_bounds__(NT)
lr_fused_kernel(const float* __restrict__ x,
                const int* __restrict__ durations,
                float* __restrict__ out,
                float* __restrict__ mask,   // nullptr if no mask
                int M)
{
    const int b    = blockIdx.z;
    const int c0   = blockIdx.y * CPB;
    const int t0   = blockIdx.x * TILE_T;
    const int tid  = threadIdx.x;
    const int lane = tid & 31;
    const int wid  = tid >> 5;

    __shared__ int s_cum[T_PH];
    __shared__ int s_wsum[NW];

    // ---- 1. block scan of durations[b] (4 elements / thread) ----
    int4 dd = reinterpret_cast<const int4*>(durations + b * T_PH)[tid];
    const int s0 = dd.x;
    const int s1 = s0 + dd.y;
    const int s2 = s1 + dd.z;
    const int s3 = s2 + dd.w;

    int v = s3;                                   // thread sum
    #pragma unroll
    for (int off = 1; off < 32; off <<= 1) {
        int n = __shfl_up_sync(0xFFFFFFFFu, v, off);
        if (lane >= off) v += n;
    }
    if (lane == 31) s_wsum[wid] = v;
    __syncthreads();
    if (wid == 0) {
        int w = (lane < NW) ? s_wsum[lane] : 0;
        #pragma unroll
        for (int off = 1; off < NW; off <<= 1) {
            int n = __shfl_up_sync(0xFFFFFFFFu, w, off);
            if (lane >= off) w += n;
        }
        if (lane < NW) s_wsum[lane] = w;
    }
    __syncthreads();

    const int base = (wid ? s_wsum[wid - 1] : 0) + (v - s3);
    reinterpret_cast<int4*>(s_cum)[tid] =
        make_int4(base + s0, base + s1, base + s2, base + s3);
    __syncthreads();

    const int total = s_cum[T_PH - 1];

    // ---- 4. mask tile (only one channel-group per (b, tile)) ----
    if (mask != nullptr && blockIdx.y == 0) {
        int tend = t0 + TILE_T; if (tend > M) tend = M;
        for (int t = t0 + tid; t < tend; t += NT)
            mask[(size_t)b * M + t] = (t >= total) ? 1.0f : 0.0f;
    }

    const int tl = t0 + tid * 4;
    if (tl >= M) return;   // (M % 4 == 0 guaranteed by dispatch -> tl+3 < M)

    // ---- 2. binary search: p = searchsorted(cum, t, 'right'), clipped ----
    int p0 = 0, p1 = 0, p2 = 0, p3 = 0;
    #pragma unroll
    for (int step = T_PH / 2; step > 0; step >>= 1) {
        if (s_cum[p0 + step - 1] <= tl + 0) p0 += step;
        if (s_cum[p1 + step - 1] <= tl + 1) p1 += step;
        if (s_cum[p2 + step - 1] <= tl + 2) p2 += step;
        if (s_cum[p3 + step - 1] <= tl + 3) p3 += step;
    }
    p0 = min(p0, T_PH - 1);
    p1 = min(p1, T_PH - 1);
    p2 = min(p2, T_PH - 1);
    p3 = min(p3, T_PH - 1);

    const bool v0 = (tl + 0 < total);
    const bool v1 = (tl + 1 < total);
    const bool v2 = (tl + 2 < total);
    const bool v3 = (tl + 3 < total);

    // ---- 3. gather: 4 channels per group -> 16 loads in flight per store burst
    const float* __restrict__ xb = x  + ((size_t)(b * C_SZ + c0)) * T_PH;
    float*       __restrict__ ob = out + ((size_t)(b * C_SZ + c0)) * M + tl;

    #pragma unroll
    for (int cc = 0; cc < CPB; cc += 4) {
        const float* __restrict__ x0 = xb + (size_t)(cc + 0) * T_PH;
        const float* __restrict__ x1 = xb + (size_t)(cc + 1) * T_PH;
        const float* __restrict__ x2 = xb + (size_t)(cc + 2) * T_PH;
        const float* __restrict__ x3 = xb + (size_t)(cc + 3) * T_PH;

        float4 a, e, f, g;
        a.x = v0 ? __ldg(x0 + p0) : 0.0f;
        a.y = v1 ? __ldg(x0 + p1) : 0.0f;
        a.z = v2 ? __ldg(x0 + p2) : 0.0f;
        a.w = v3 ? __ldg(x0 + p3) : 0.0f;
        e.x = v0 ? __ldg(x1 + p0) : 0.0f;
        e.y = v1 ? __ldg(x1 + p1) : 0.0f;
        e.z = v2 ? __ldg(x1 + p2) : 0.0f;
        e.w = v3 ? __ldg(x1 + p3) : 0.0f;
        f.x = v0 ? __ldg(x2 + p0) : 0.0f;
        f.y = v1 ? __ldg(x2 + p1) : 0.0f;
        f.z = v2 ? __ldg(x2 + p2) : 0.0f;
        f.w = v3 ? __ldg(x2 + p3) : 0.0f;
        g.x = v0 ? __ldg(x3 + p0) : 0.0f;
        g.y = v1 ? __ldg(x3 + p1) : 0.0f;
        g.z = v2 ? __ldg(x3 + p2) : 0.0f;
        g.w = v3 ? __ldg(x3 + p3) : 0.0f;

        *reinterpret_cast<float4*>(ob + (size_t)(cc + 0) * M) = a;
        *reinterpret_cast<float4*>(ob + (size_t)(cc + 1) * M) = e;
        *reinterpret_cast<float4*>(ob + (size_t)(cc + 2) * M) = f;
        *reinterpret_cast<float4*>(ob + (size_t)(cc + 3) * M) = g;
    }
}

// -----------------------------------------------------------------------------
// Scalar fallback (only if M % 4 != 0) — same fused structure, 1 frame/thread.
// -----------------------------------------------------------------------------
__global__ void __launch_bounds__(NT)
lr_fused_scalar_kernel(const float* __restrict__ x,
                       const int* __restrict__ durations,
                       float* __restrict__ out,
                       float* __restrict__ mask,
                       int M)
{
    const int b    = blockIdx.z;
    const int c0   = blockIdx.y * CPB;
    const int t0   = blockIdx.x * NT;
    const int tid  = threadIdx.x;
    const int lane = tid & 31;
    const int wid  = tid >> 5;

    __shared__ int s_cum[T_PH];
    __shared__ int s_wsum[NW];

    int4 dd = reinterpret_cast<const int4*>(durations + b * T_PH)[tid];
    const int s0 = dd.x, s1 = s0 + dd.y, s2 = s1 + dd.z, s3 = s2 + dd.w;
    int v = s3;
    #pragma unroll
    for (int off = 1; off < 32; off <<= 1) {
        int n = __shfl_up_sync(0xFFFFFFFFu, v, off);
        if (lane >= off) v += n;
    }
    if (lane == 31) s_wsum[wid] = v;
    __syncthreads();
    if (wid == 0) {
        int w = (lane < NW) ? s_wsum[lane] : 0;
        #pragma unroll
        for (int off = 1; off < NW; off <<= 1) {
            int n = __shfl_up_sync(0xFFFFFFFFu, w, off);
            if (lane >= off) w += n;
        }
        if (lane < NW) s_wsum[lane] = w;
    }
    __syncthreads();
    const int base = (wid ? s_wsum[wid - 1] : 0) + (v - s3);
    reinterpret_cast<int4*>(s_cum)[tid] =
        make_int4(base + s0, base + s1, base + s2, base + s3);
    __syncthreads();

    const int total = s_cum[T_PH - 1];
    const int t = t0 + tid;

    if (mask != nullptr && blockIdx.y == 0 && t < M)
        mask[(size_t)b * M + t] = (t >= total) ? 1.0f : 0.0f;

    if (t >= M) return;

    int p = 0;
    #pragma unroll
    for (int step = T_PH / 2; step > 0; step >>= 1)
        if (s_cum[p + step - 1] <= t) p += step;
    p = min(p, T_PH - 1);
    const bool val = (t < total);

    const float* xb = x + ((size_t)(b * C_SZ + c0)) * T_PH;
    float* ob = out + ((size_t)(b * C_SZ + c0)) * M + t;
    #pragma unroll
    for (int cc = 0; cc < CPB; ++cc)
        ob[(size_t)cc * M] = val ? __ldg(xb + (size_t)cc * T_PH + p) : 0.0f;
}

// -----------------------------------------------------------------------------
// Launch
// -----------------------------------------------------------------------------
extern "C" void kernel_launch(void* const* d_in, const int* in_sizes, int n_in,
                              void* d_out, int out_size)
{
    const float* x         = (const float*)d_in[0];
    const int*   durations = (const int*)d_in[1];
    float* out = (float*)d_out;

    // Resolve M and layout: tuple  out[B,C,M] ++ mask[B,M] => B*M*(C+1);
    // fallback out-only => B*M*C.
    long long os = (long long)out_size;
    int M;
    float* mask_ptr = nullptr;
    if (os % ((long long)B_SZ * (C_SZ + 1)) == 0) {
        M = (int)(os / ((long long)B_SZ * (C_SZ + 1)));
        mask_ptr = out + (size_t)B_SZ * C_SZ * M;
    } else {
        M = (int)(os / ((long long)B_SZ * C_SZ));
    }

    if ((M & 3) == 0) {
        dim3 grid((M + TILE_T - 1) / TILE_T, C_SZ / CPB, B_SZ);
        lr_fused_kernel<<<grid, NT>>>(x, durations, out, mask_ptr, M);
    } else {
        dim3 grid((M + NT - 1) / NT, C_SZ / CPB, B_SZ);
        lr_fused_scalar_kernel<<<grid, NT>>>(x, durations, out, mask_ptr, M);
    }
}